// round 8
// baseline (speedup 1.0000x reference)
#include <cuda_runtime.h>
#include <cuda_bf16.h>
#include <math.h>

#define BMAX 2048
#define KD   256
#define PD   256
#define SD   10
#define SP   5              // sample pairs
#define SROWS 8             // k-rows per pipeline stage
#define NIT  (KD / SROWS)   // 32 stages
#define STAGE_FLOATS (SROWS * PD)      // 2048

// per-batch partial results (allocation-free scratch)
__device__ float g_pen[BMAX];
__device__ float g_lmse[BMAX];

typedef unsigned long long u64;

__device__ __forceinline__ u64 ffma2(u64 a, u64 b, u64 c) {
    u64 d;
    asm("fma.rn.f32x2 %0, %1, %2, %3;" : "=l"(d) : "l"(a), "l"(b), "l"(c));
    return d;
}
__device__ __forceinline__ u64 bcast2(float p) {
    u64 d; unsigned u = __float_as_uint(p);
    asm("mov.b64 %0, {%1, %1};" : "=l"(d) : "r"(u));
    return d;
}
__device__ __forceinline__ void cpa16(unsigned saddr, const float* g) {
    asm volatile("cp.async.cg.shared.global [%0], [%1], 16;" :: "r"(saddr), "l"(g));
}
__device__ __forceinline__ void cpa_commit() {
    asm volatile("cp.async.commit_group;");
}

__global__ __launch_bounds__(256, 4)
void vil_main_kernel(const float* __restrict__ y_pred,
                     const float* __restrict__ y_true,
                     const float* __restrict__ Pp,
                     const float* __restrict__ params,
                     const float* __restrict__ Xs)
{
    const int b    = blockIdx.x;
    const int tid  = threadIdx.x;
    const int lane = tid & 31;
    const int w    = tid >> 5;

    __shared__ float2 xsp[SP][KD];                        // masked X, 10 KB
    __shared__ __align__(16) float pool[4 * STAGE_FLOATS]; // 32 KB: P stages, later cacc
    __shared__ float hms[SD];

    float (*cacc)[PD] = (float (*)[PD])pool;              // [SD][PD] alias (post-GEMM)

    const int n  = (int)params[b * 3 + 0];
    const int kb = (int)params[b * 3 + 1];
    const int mb = (int)params[b * 3 + 2];
    const int nk = n - kb;

    const float*   Pbase     = Pp + (size_t)b * KD * PD;
    const unsigned pool_base = (unsigned)__cvta_generic_to_shared(pool);

    // per-warp cp.async geometry: warp w owns columns [32w, 32w+32)
    // lane l handles rows r = l>>2, col chunks c0 = l&3 and c0+4 (16B each)
    const int r_   = lane >> 2;
    const int c0_  = (lane & 3) * 4;
    const int colb = 32 * w;
    // within-stage float offsets for this lane's two 16B chunks
    const int soff0 = r_ * PD + colb + c0_;
    const int soff1 = soff0 + 16;

    // ---- prologue: each warp issues ITS columns of stages 0..2 ----
#pragma unroll
    for (int it = 0; it < 3; it++) {
        unsigned dst = pool_base + ((it & 3) * STAGE_FLOATS) * 4;
        const float* src = Pbase + it * SROWS * PD;
        cpa16(dst + soff0 * 4, src + soff0);
        cpa16(dst + soff1 * 4, src + soff1);
        cpa_commit();
    }

    // ---- load X[b], masked, packed as (x[2sp][k], x[2sp+1][k]) ----
    const float* Xb = Xs + (size_t)b * SD * KD;
    for (int idx = tid; idx < SP * KD; idx += 256) {
        int s = idx >> 8;
        int k = idx & (KD - 1);
        float a = Xb[(2 * s)     * KD + k];
        float c = Xb[(2 * s + 1) * KD + k];
        if (k >= kb) { a = 0.0f; c = 0.0f; }
        xsp[s][k] = make_float2(a, c);
    }
    __syncthreads();   // publish X (the only block barrier before the epilogue)

    u64 acc[SP];
#pragma unroll
    for (int s = 0; s < SP; s++) acc[s] = 0ull;

    // ---- barrier-free pipelined GEMM mainloop (warp-private columns) ----
    for (int it = 0; it < NIT; it++) {
        // warp-local wait: stage `it` (this warp's columns) resident
        if (it <= NIT - 3)      asm volatile("cp.async.wait_group 2;");
        else if (it == NIT - 2) asm volatile("cp.async.wait_group 1;");
        else                    asm volatile("cp.async.wait_group 0;");

        const float* st = pool + (it & 3) * STAGE_FLOATS;
        const int k8 = it * SROWS;

        // hoist this warp's 8 P values (col = tid's own column)
        float pv[SROWS];
#pragma unroll
        for (int u = 0; u < SROWS; u++) pv[u] = st[u * PD + tid];

#pragma unroll
        for (int u = 0; u < SROWS; u += 2) {
            u64 p0 = bcast2(pv[u]);
            u64 p1 = bcast2(pv[u + 1]);
#pragma unroll
            for (int s = 0; s < SP; s++) {
                // one LDS.128: x sample-pairs for k8+u, k8+u+1 (broadcast, conflict-free)
                const ulonglong2 xq = *(const ulonglong2*)&xsp[s][k8 + u];
                acc[s] = ffma2(xq.x, p0, acc[s]);
                acc[s] = ffma2(xq.y, p1, acc[s]);
            }
        }

        // issue stage it+3 into ring slot (it-1)&3 — this warp's columns only,
        // already fully consumed by this warp (sequential), so no hazard.
        if (it + 3 < NIT) {
            unsigned dst = pool_base + (((it + 3) & 3) * STAGE_FLOATS) * 4;
            const float* src = Pbase + (it + 3) * SROWS * PD;
            cpa16(dst + soff0 * 4, src + soff0);
            cpa16(dst + soff1 * 4, src + soff1);
            cpa_commit();
        }
    }

    // ---- unpack results into cacc (warp-private columns; alias-safe) ----
#pragma unroll
    for (int s = 0; s < SP; s++) {
        float2 v = *(float2*)&acc[s];
        cacc[2 * s][tid]     = v.x;
        cacc[2 * s + 1][tid] = v.y;
    }
    __syncthreads();

    // ---- per-sample top-(m+1) via iterative max extraction (1 warp / sample) ----
    for (int s = w; s < SD; s += 8) {
        float v[16];
#pragma unroll
        for (int i = 0; i < 8; i++) {
            int idx = lane + 32 * i;
            float2 xv = xsp[s >> 1][idx];
            float x = (s & 1) ? xv.y : xv.x;
            v[i] = (idx < kb) ? fabsf(x) : -1.0f;
        }
#pragma unroll
        for (int i = 0; i < 8; i++) {
            int j = lane + 32 * i;
            v[8 + i] = (j < nk) ? fabsf(cacc[s][j]) : -1.0f;
        }

        float cmax = 0.0f, cm = 0.0f;
        for (int pass = 0;; pass++) {
            float lm = v[0];
#pragma unroll
            for (int i = 1; i < 16; i++) lm = fmaxf(lm, v[i]);
            float wm = lm;
#pragma unroll
            for (int off = 16; off; off >>= 1)
                wm = fmaxf(wm, __shfl_xor_sync(0xffffffffu, wm, off));
            if (pass == 0)  cmax = wm;
            if (pass == mb) { cm = wm; break; }
            // remove exactly ONE instance of wm (matches sort semantics on ties)
            unsigned bal = __ballot_sync(0xffffffffu, lm == wm);
            int src = __ffs(bal) - 1;
            if (lane == src) {
                bool done = false;
#pragma unroll
                for (int i = 0; i < 16; i++) {
                    if (!done && v[i] == wm) { v[i] = -3.0e38f; done = true; }
                }
            }
        }
        if (lane == 0) hms[s] = cmax / (cm + 1e-9f);
    }
    __syncthreads();

    if (tid == 0) {
        float mh = hms[0];
#pragma unroll
        for (int s = 1; s < SD; s++) mh = fmaxf(mh, hms[s]);
        float yp = y_pred[b];
        float pen = ((mb + 1) <= n) ? fmaxf(mh - yp, 0.0f) : 0.0f;
        g_pen[b] = pen;
        float lp = log2f(fmaxf(yp, 1e-9f));
        float lt = log2f(fmaxf(y_true[b], 1e-9f));
        float d  = lt - lp;
        g_lmse[b] = d * d;
    }
}

__global__ __launch_bounds__(256)
void vil_finalize_kernel(float* __restrict__ out, int out_size, int Bn)
{
    __shared__ float sp[256], sl[256];
    int t = threadIdx.x;
    float p = 0.0f, l = 0.0f;
    for (int i = t; i < Bn; i += 256) { p += g_pen[i]; l += g_lmse[i]; }
    sp[t] = p; sl[t] = l;
    __syncthreads();
    for (int o = 128; o; o >>= 1) {
        if (t < o) { sp[t] += sp[t + o]; sl[t] += sl[t + o]; }
        __syncthreads();
    }
    if (t == 0) {
        float lmse = sl[0] / (float)Bn;
        float viol = sp[0] / (float)Bn;
        float tot  = lmse + 0.5f * viol;
        if (out_size > 0) out[0] = tot;
        if (out_size > 1) out[1] = lmse;
        if (out_size > 2) out[2] = viol;
    }
}

// empty pad kernels: make launches-per-replay = 5 so ncu's skip-5 lands on
// vil_main_kernel (5 mod 5 == 0) instead of the finalize kernel.
__global__ void vil_pad_kernel() {}

extern "C" void kernel_launch(void* const* d_in, const int* in_sizes, int n_in,
                              void* d_out, int out_size)
{
    const float* y_pred = (const float*)d_in[0];
    const float* y_true = (const float*)d_in[1];
    const float* Pp     = (const float*)d_in[2];
    const float* params = (const float*)d_in[3];
    const float* Xs     = (const float*)d_in[4];
    float* out = (float*)d_out;

    int Bn = in_sizes[0];
    if (Bn > BMAX) Bn = BMAX;

    vil_main_kernel<<<Bn, 256>>>(y_pred, y_true, Pp, params, Xs);
    vil_finalize_kernel<<<1, 256>>>(out, out_size, Bn);
    vil_pad_kernel<<<1, 32>>>();
    vil_pad_kernel<<<1, 32>>>();
    vil_pad_kernel<<<1, 32>>>();
}

// round 9
// speedup vs baseline: 1.1407x; 1.1407x over previous
#include <cuda_runtime.h>
#include <cuda_bf16.h>
#include <math.h>

#define BMAX 2048
#define KD   256
#define PD   256
#define SD   10
#define SP   5              // sample pairs
#define SROWS 8             // k-rows per pipeline stage
#define NIT  (KD / SROWS)   // 32 stages
#define STAGE_FLOATS (SROWS * PD)      // 2048
#define NTHR 128            // threads per CTA (2 columns each)

// per-batch partial results (allocation-free scratch)
__device__ float g_pen[BMAX];
__device__ float g_lmse[BMAX];

typedef unsigned long long u64;

__device__ __forceinline__ u64 ffma2(u64 a, u64 b, u64 c) {
    u64 d;
    asm("fma.rn.f32x2 %0, %1, %2, %3;" : "=l"(d) : "l"(a), "l"(b), "l"(c));
    return d;
}
__device__ __forceinline__ u64 bcast2(float p) {
    u64 d; unsigned u = __float_as_uint(p);
    asm("mov.b64 %0, {%1, %1};" : "=l"(d) : "r"(u));
    return d;
}
__device__ __forceinline__ void cpa16(unsigned saddr, const float* g) {
    asm volatile("cp.async.cg.shared.global [%0], [%1], 16;" :: "r"(saddr), "l"(g));
}
__device__ __forceinline__ void cpa_commit() {
    asm volatile("cp.async.commit_group;");
}

__global__ __launch_bounds__(NTHR, 5)
void vil_main_kernel(const float* __restrict__ y_pred,
                     const float* __restrict__ y_true,
                     const float* __restrict__ Pp,
                     const float* __restrict__ params,
                     const float* __restrict__ Xs)
{
    const int b    = blockIdx.x;
    const int tid  = threadIdx.x;
    const int lane = tid & 31;
    const int w    = tid >> 5;

    __shared__ float2 xsp[SP][KD];                         // masked X, 10 KB
    __shared__ __align__(16) float pool[4 * STAGE_FLOATS]; // 32 KB: P stages, later cacc
    __shared__ float hms[SD];

    float (*cacc)[PD] = (float (*)[PD])pool;               // [SD][PD] alias (post-GEMM)

    const int n  = (int)params[b * 3 + 0];
    const int kb = (int)params[b * 3 + 1];
    const int mb = (int)params[b * 3 + 2];
    const int nk = n - kb;

    const float*   Pbase     = Pp + (size_t)b * KD * PD;
    const unsigned pool_base = (unsigned)__cvta_generic_to_shared(pool);

    // per-warp cp.async geometry: warp w owns columns [64w, 64w+64)
    // per stage: 8 rows x 64 cols = 2 KB = 128 x 16B chunks; 4 chunks per lane.
    // chunk c = lane + 32*i : row = c>>4, col-offset = (c&15)*4
    int soff[4];
#pragma unroll
    for (int i = 0; i < 4; i++) {
        int c = lane + 32 * i;
        soff[i] = (c >> 4) * PD + 64 * w + (c & 15) * 4;
    }

    // ---- prologue: each warp issues ITS columns of stages 0..2 ----
#pragma unroll
    for (int it = 0; it < 3; it++) {
        unsigned dst = pool_base + ((it & 3) * STAGE_FLOATS) * 4;
        const float* src = Pbase + it * SROWS * PD;
#pragma unroll
        for (int i = 0; i < 4; i++) cpa16(dst + soff[i] * 4, src + soff[i]);
        cpa_commit();
    }

    // ---- load X[b], masked, packed as (x[2sp][k], x[2sp+1][k]) ----
    const float* Xb = Xs + (size_t)b * SD * KD;
    for (int idx = tid; idx < SP * KD; idx += NTHR) {
        int s = idx >> 8;
        int k = idx & (KD - 1);
        float a = Xb[(2 * s)     * KD + k];
        float c = Xb[(2 * s + 1) * KD + k];
        if (k >= kb) { a = 0.0f; c = 0.0f; }
        xsp[s][k] = make_float2(a, c);
    }
    __syncthreads();   // publish X (only block barrier before epilogue)

    // thread owns columns 2*tid and 2*tid+1
    u64 acc0[SP], acc1[SP];
#pragma unroll
    for (int s = 0; s < SP; s++) { acc0[s] = 0ull; acc1[s] = 0ull; }

    // ---- barrier-free pipelined GEMM mainloop (warp-private columns) ----
    for (int it = 0; it < NIT; it++) {
        if (it <= NIT - 3)      asm volatile("cp.async.wait_group 2;");
        else if (it == NIT - 2) asm volatile("cp.async.wait_group 1;");
        else                    asm volatile("cp.async.wait_group 0;");

        const float* st = pool + (it & 3) * STAGE_FLOATS;
        const int k8 = it * SROWS;

        // hoist this thread's 8 P column-pairs (LDS.64, conflict-free)
        float2 pv[SROWS];
#pragma unroll
        for (int u = 0; u < SROWS; u++)
            pv[u] = *(const float2*)&st[u * PD + 2 * tid];

#pragma unroll
        for (int u = 0; u < SROWS; u += 2) {
            u64 a0 = bcast2(pv[u].x);       // P[k][2t]
            u64 a1 = bcast2(pv[u].y);       // P[k][2t+1]
            u64 b0 = bcast2(pv[u + 1].x);   // P[k+1][2t]
            u64 b1 = bcast2(pv[u + 1].y);   // P[k+1][2t+1]
#pragma unroll
            for (int s = 0; s < SP; s++) {
                // one LDS.128: x sample-pairs for k8+u, k8+u+1 (broadcast)
                const ulonglong2 xq = *(const ulonglong2*)&xsp[s][k8 + u];
                acc0[s] = ffma2(xq.x, a0, acc0[s]);
                acc1[s] = ffma2(xq.x, a1, acc1[s]);
                acc0[s] = ffma2(xq.y, b0, acc0[s]);
                acc1[s] = ffma2(xq.y, b1, acc1[s]);
            }
        }

        // issue stage it+3 into ring slot (it-1)&3 — this warp's columns only,
        // already consumed by this warp (sequential), so no cross-warp hazard.
        if (it + 3 < NIT) {
            unsigned dst = pool_base + (((it + 3) & 3) * STAGE_FLOATS) * 4;
            const float* src = Pbase + (it + 3) * SROWS * PD;
#pragma unroll
            for (int i = 0; i < 4; i++) cpa16(dst + soff[i] * 4, src + soff[i]);
            cpa_commit();
        }
    }

    // ---- unpack results into cacc (warp-private columns; alias-safe:
    //      cacc occupies ring slots 0/1, last stage read was slot 3) ----
#pragma unroll
    for (int s = 0; s < SP; s++) {
        float2 v0 = *(float2*)&acc0[s];   // (sample 2s, 2s+1) @ col 2t
        float2 v1 = *(float2*)&acc1[s];   // (sample 2s, 2s+1) @ col 2t+1
        *(float2*)&cacc[2 * s][2 * tid]     = make_float2(v0.x, v1.x);
        *(float2*)&cacc[2 * s + 1][2 * tid] = make_float2(v0.y, v1.y);
    }
    __syncthreads();

    // ---- per-sample top-(m+1) via iterative max extraction (1 warp / sample) ----
    for (int s = w; s < SD; s += 4) {
        float v[16];
#pragma unroll
        for (int i = 0; i < 8; i++) {
            int idx = lane + 32 * i;
            float2 xv = xsp[s >> 1][idx];
            float x = (s & 1) ? xv.y : xv.x;
            v[i] = (idx < kb) ? fabsf(x) : -1.0f;
        }
#pragma unroll
        for (int i = 0; i < 8; i++) {
            int j = lane + 32 * i;
            v[8 + i] = (j < nk) ? fabsf(cacc[s][j]) : -1.0f;
        }

        float cmax = 0.0f, cm = 0.0f;
        for (int pass = 0;; pass++) {
            float lm = v[0];
#pragma unroll
            for (int i = 1; i < 16; i++) lm = fmaxf(lm, v[i]);
            float wm = lm;
#pragma unroll
            for (int off = 16; off; off >>= 1)
                wm = fmaxf(wm, __shfl_xor_sync(0xffffffffu, wm, off));
            if (pass == 0)  cmax = wm;
            if (pass == mb) { cm = wm; break; }
            // remove exactly ONE instance of wm (matches sort semantics on ties)
            unsigned bal = __ballot_sync(0xffffffffu, lm == wm);
            int src = __ffs(bal) - 1;
            if (lane == src) {
                bool done = false;
#pragma unroll
                for (int i = 0; i < 16; i++) {
                    if (!done && v[i] == wm) { v[i] = -3.0e38f; done = true; }
                }
            }
        }
        if (lane == 0) hms[s] = cmax / (cm + 1e-9f);
    }
    __syncthreads();

    if (tid == 0) {
        float mh = hms[0];
#pragma unroll
        for (int s = 1; s < SD; s++) mh = fmaxf(mh, hms[s]);
        float yp = y_pred[b];
        float pen = ((mb + 1) <= n) ? fmaxf(mh - yp, 0.0f) : 0.0f;
        g_pen[b] = pen;
        float lp = log2f(fmaxf(yp, 1e-9f));
        float lt = log2f(fmaxf(y_true[b], 1e-9f));
        float d  = lt - lp;
        g_lmse[b] = d * d;
    }
}

__global__ __launch_bounds__(256)
void vil_finalize_kernel(float* __restrict__ out, int out_size, int Bn)
{
    __shared__ float sp[256], sl[256];
    int t = threadIdx.x;
    float p = 0.0f, l = 0.0f;
    for (int i = t; i < Bn; i += 256) { p += g_pen[i]; l += g_lmse[i]; }
    sp[t] = p; sl[t] = l;
    __syncthreads();
    for (int o = 128; o; o >>= 1) {
        if (t < o) { sp[t] += sp[t + o]; sl[t] += sl[t + o]; }
        __syncthreads();
    }
    if (t == 0) {
        float lmse = sl[0] / (float)Bn;
        float viol = sp[0] / (float)Bn;
        float tot  = lmse + 0.5f * viol;
        if (out_size > 0) out[0] = tot;
        if (out_size > 1) out[1] = lmse;
        if (out_size > 2) out[2] = viol;
    }
}

extern "C" void kernel_launch(void* const* d_in, const int* in_sizes, int n_in,
                              void* d_out, int out_size)
{
    const float* y_pred = (const float*)d_in[0];
    const float* y_true = (const float*)d_in[1];
    const float* Pp     = (const float*)d_in[2];
    const float* params = (const float*)d_in[3];
    const float* Xs     = (const float*)d_in[4];
    float* out = (float*)d_out;

    int Bn = in_sizes[0];
    if (Bn > BMAX) Bn = BMAX;

    vil_main_kernel<<<Bn, NTHR>>>(y_pred, y_true, Pp, params, Xs);
    vil_finalize_kernel<<<1, 256>>>(out, out_size, Bn);
}